// round 15
// baseline (speedup 1.0000x reference)
#include <cuda_runtime.h>

// ---------------------------------------------------------------------------
// MultiHeadAttention: x@W_qkv+b -> flash attention -> @W_out+b
// B=4, S=2048, HID=1024, H=16, D=64. All fp32.
// Uses sm_103a packed fp32 FMA (fma.rn.f32x2) for 2x fp32 throughput.
// ---------------------------------------------------------------------------

#define BATCH 4
#define SEQ   2048
#define HID   1024
#define HEADS 16
#define HDIM  64
#define MTOT  (BATCH * SEQ)   // 8192

typedef unsigned long long ULL;

// ------------------------- f32x2 helpers (sm_103a) -------------------------
__device__ __forceinline__ ULL pack2(float lo, float hi) {
    ULL r;
    asm("mov.b64 %0, {%1,%2};" : "=l"(r)
        : "r"(__float_as_uint(lo)), "r"(__float_as_uint(hi)));
    return r;
}
__device__ __forceinline__ float2 unpack2(ULL v) {
    unsigned int lo, hi;
    asm("mov.b64 {%0,%1}, %2;" : "=r"(lo), "=r"(hi) : "l"(v));
    return make_float2(__uint_as_float(lo), __uint_as_float(hi));
}
__device__ __forceinline__ void ffma2(ULL& d, ULL a, ULL b) {
    asm("fma.rn.f32x2 %0, %1, %2, %0;" : "+l"(d) : "l"(a), "l"(b));
}
__device__ __forceinline__ void fmul2(ULL& d, ULL a) {
    asm("mul.rn.f32x2 %0, %0, %1;" : "+l"(d) : "l"(a));
}

// ------------------------- scratch (device globals) ------------------------
__device__ __align__(128) float g_Q[BATCH * HEADS * SEQ * HDIM];
__device__ __align__(128) float g_K[BATCH * HEADS * SEQ * HDIM];
__device__ __align__(128) float g_V[BATCH * HEADS * SEQ * HDIM];
__device__ __align__(128) float g_attn[MTOT * HID];

// ------------------------- QKV scatter epilogue ----------------------------
__device__ __forceinline__ void store_qkv(int row, int n, float4 v) {
    // n in [0, 3072): chunk = n/1024 (0=Q,1=K,2=V), h = (n%1024)/64, d = n%64
    int chunk = n >> 10;
    int h = (n >> 6) & (HEADS - 1);
    int d = n & (HDIM - 1);
    int b = row >> 11;           // row / SEQ
    int s = row & (SEQ - 1);
    float* dst = (chunk == 0) ? g_Q : (chunk == 1) ? g_K : g_V;
    long idx = ((long)((b * HEADS + h) * SEQ + s) << 6) + d;
    *(float4*)&dst[idx] = v;
}

// ------------------------- SGEMM 128x128x16, 8x8/thread --------------------
// MODE 0: C[M,N] = A@B + bias  (A = g_attn when Ain==nullptr path? no: MODE)
// MODE 1: scatter into g_Q/g_K/g_V
template <int MODE>
__global__ __launch_bounds__(256, 2)
void sgemm_kernel(const float* __restrict__ Ain,
                  const float* __restrict__ Bmat,
                  const float* __restrict__ bias,
                  float* __restrict__ C,
                  int N, int K)
{
    __shared__ __align__(16) float As[16][128];  // k-major (transposed A tile)
    __shared__ __align__(16) float Bs[16][128];

    const float* A = (MODE == 0) ? (const float*)g_attn : Ain;

    int t  = threadIdx.x;
    int tx = t & 15;
    int ty = t >> 4;
    int m0 = blockIdx.y * 128;
    int n0 = blockIdx.x * 128;

    // global load assignments
    int ar = t >> 1;            // 0..127 (row within A tile)
    int ac = (t & 1) * 8;       // 0 or 8 (k offset)
    int br = t >> 4;            // 0..15 (k row of B tile)
    int bc = (t & 15) * 4;      // 0..60

    const float* Ap = A + (long)(m0 + ar) * K + ac;
    const float* Bp = Bmat + (long)br * N + n0 + bc;

    float4 ra0 = *(const float4*)(Ap);
    float4 ra1 = *(const float4*)(Ap + 4);
    float4 rb0 = *(const float4*)(Bp);
    float4 rb1 = *(const float4*)(Bp + 64);

    ULL acc[8][4];
#pragma unroll
    for (int i = 0; i < 8; i++)
#pragma unroll
        for (int j = 0; j < 4; j++) acc[i][j] = 0ULL;

    int nk = K >> 4;
    for (int kt = 0; kt < nk; kt++) {
        __syncthreads();
        // store staged tile (A transposed to k-major)
        As[ac + 0][ar] = ra0.x; As[ac + 1][ar] = ra0.y;
        As[ac + 2][ar] = ra0.z; As[ac + 3][ar] = ra0.w;
        As[ac + 4][ar] = ra1.x; As[ac + 5][ar] = ra1.y;
        As[ac + 6][ar] = ra1.z; As[ac + 7][ar] = ra1.w;
        *(float4*)&Bs[br][bc]      = rb0;
        *(float4*)&Bs[br][bc + 64] = rb1;
        __syncthreads();

        // prefetch next tile into registers (overlaps with compute)
        if (kt + 1 < nk) {
            const float* Ap2 = Ap + (kt + 1) * 16;
            const float* Bp2 = Bp + (long)(kt + 1) * 16 * N;
            ra0 = *(const float4*)(Ap2);
            ra1 = *(const float4*)(Ap2 + 4);
            rb0 = *(const float4*)(Bp2);
            rb1 = *(const float4*)(Bp2 + 64);
        }

#pragma unroll
        for (int k = 0; k < 16; k++) {
            float4 a0 = *(const float4*)&As[k][ty * 4];
            float4 a1 = *(const float4*)&As[k][64 + ty * 4];
            ulonglong2 b0 = *(const ulonglong2*)&Bs[k][tx * 4];
            ulonglong2 b1 = *(const ulonglong2*)&Bs[k][64 + tx * 4];
            ULL ad[8];
            ad[0] = pack2(a0.x, a0.x); ad[1] = pack2(a0.y, a0.y);
            ad[2] = pack2(a0.z, a0.z); ad[3] = pack2(a0.w, a0.w);
            ad[4] = pack2(a1.x, a1.x); ad[5] = pack2(a1.y, a1.y);
            ad[6] = pack2(a1.z, a1.z); ad[7] = pack2(a1.w, a1.w);
#pragma unroll
            for (int i = 0; i < 8; i++) {
                ffma2(acc[i][0], ad[i], b0.x);
                ffma2(acc[i][1], ad[i], b0.y);
                ffma2(acc[i][2], ad[i], b1.x);
                ffma2(acc[i][3], ad[i], b1.y);
            }
        }
    }

    // epilogue
    int c0 = n0 + tx * 4;
    int c1 = n0 + 64 + tx * 4;
    float4 bi0 = *(const float4*)&bias[c0];
    float4 bi1 = *(const float4*)&bias[c1];
#pragma unroll
    for (int i = 0; i < 8; i++) {
        int lr = (i < 4) ? (ty * 4 + i) : (64 + ty * 4 + i - 4);
        int gr = m0 + lr;
        float2 p0 = unpack2(acc[i][0]);
        float2 p1 = unpack2(acc[i][1]);
        float2 p2 = unpack2(acc[i][2]);
        float2 p3 = unpack2(acc[i][3]);
        float4 v0 = make_float4(p0.x + bi0.x, p0.y + bi0.y, p1.x + bi0.z, p1.y + bi0.w);
        float4 v1 = make_float4(p2.x + bi1.x, p2.y + bi1.y, p3.x + bi1.z, p3.y + bi1.w);
        if (MODE == 0) {
            *(float4*)&C[(long)gr * N + c0] = v0;
            *(float4*)&C[(long)gr * N + c1] = v1;
        } else {
            store_qkv(gr, c0, v0);
            store_qkv(gr, c1, v1);
        }
    }
}

// ------------------------- Flash attention (fp32) --------------------------
// One CTA per (b, h, 64-query tile). 256 threads = 16x16 logical grid.
// Smem: Qt(k-major) 16KB + Kt(k-major) 16KB + Vs 16KB + Ps 16KB = 64KB dynamic.
__global__ __launch_bounds__(256)
void attn_kernel()
{
    extern __shared__ __align__(16) float sm[];
    float* Qt = sm;            // [64 k][64 row]
    float* Kt = sm + 4096;     // [64 k][64 col]
    float* Vs = sm + 8192;     // [64 kv][64 d]
    float* Ps = sm + 12288;    // [64 row][64 kv]

    int t  = threadIdx.x;
    int tx = t & 15;
    int ty = t >> 4;
    int qt = blockIdx.x;
    int h  = blockIdx.y;
    int b  = blockIdx.z;

    long bh_base = (long)(b * HEADS + h) * SEQ * HDIM;
    const float* Qg = g_Q + bh_base + (long)qt * 64 * HDIM;
    const float* Kg = g_K + bh_base;
    const float* Vg = g_V + bh_base;

    int lr = t >> 2;            // 0..63
    int lc = (t & 3) * 16;      // 0,16,32,48

    // load Q tile transposed & pre-scaled by 1/sqrt(64)
#pragma unroll
    for (int q = 0; q < 4; q++) {
        int c = lc + q * 4;
        float4 v = *(const float4*)&Qg[lr * HDIM + c];
        Qt[(c + 0) * 64 + lr] = v.x * 0.125f;
        Qt[(c + 1) * 64 + lr] = v.y * 0.125f;
        Qt[(c + 2) * 64 + lr] = v.z * 0.125f;
        Qt[(c + 3) * 64 + lr] = v.w * 0.125f;
    }

    const float NEG_INF = __int_as_float(0xff800000);
    float mrow[4], lrow[4];
    ULL o2[4][2];
#pragma unroll
    for (int i = 0; i < 4; i++) {
        mrow[i] = NEG_INF; lrow[i] = 0.0f;
        o2[i][0] = 0ULL;   o2[i][1] = 0ULL;
    }

    for (int kt = 0; kt < SEQ / 64; kt++) {
        __syncthreads();   // previous PV done reading Vs/Ps (and Qt on iter 0)
        const float* Kgt = Kg + (long)kt * 64 * HDIM;
        const float* Vgt = Vg + (long)kt * 64 * HDIM;
#pragma unroll
        for (int q = 0; q < 4; q++) {
            int c = lc + q * 4;
            float4 kv = *(const float4*)&Kgt[lr * HDIM + c];
            Kt[(c + 0) * 64 + lr] = kv.x;
            Kt[(c + 1) * 64 + lr] = kv.y;
            Kt[(c + 2) * 64 + lr] = kv.z;
            Kt[(c + 3) * 64 + lr] = kv.w;
            *(float4*)&Vs[lr * 64 + c] = *(const float4*)&Vgt[lr * HDIM + c];
        }
        __syncthreads();

        // S = (Q*scale) @ K^T  -- 4x4 per thread, f32x2 packed
        ULL s2[4][2] = {{0ULL, 0ULL}, {0ULL, 0ULL}, {0ULL, 0ULL}, {0ULL, 0ULL}};
#pragma unroll 8
        for (int k = 0; k < 64; k++) {
            float4 a = *(const float4*)&Qt[k * 64 + ty * 4];
            ulonglong2 bv = *(const ulonglong2*)&Kt[k * 64 + tx * 4];
            ULL a0 = pack2(a.x, a.x), a1 = pack2(a.y, a.y);
            ULL a2 = pack2(a.z, a.z), a3 = pack2(a.w, a.w);
            ffma2(s2[0][0], a0, bv.x); ffma2(s2[0][1], a0, bv.y);
            ffma2(s2[1][0], a1, bv.x); ffma2(s2[1][1], a1, bv.y);
            ffma2(s2[2][0], a2, bv.x); ffma2(s2[2][1], a2, bv.y);
            ffma2(s2[3][0], a3, bv.x); ffma2(s2[3][1], a3, bv.y);
        }

        // online softmax (row stats replicated across the 16 tx lanes)
#pragma unroll
        for (int ii = 0; ii < 4; ii++) {
            float2 q0 = unpack2(s2[ii][0]);
            float2 q1 = unpack2(s2[ii][1]);
            float tmax = fmaxf(fmaxf(q0.x, q0.y), fmaxf(q1.x, q1.y));
#pragma unroll
            for (int off = 1; off < 16; off <<= 1)
                tmax = fmaxf(tmax, __shfl_xor_sync(0xffffffffu, tmax, off));
            float mn   = fmaxf(mrow[ii], tmax);
            float corr = __expf(mrow[ii] - mn);
            float p0 = __expf(q0.x - mn);
            float p1 = __expf(q0.y - mn);
            float p2 = __expf(q1.x - mn);
            float p3 = __expf(q1.y - mn);
            float rs = (p0 + p1) + (p2 + p3);
#pragma unroll
            for (int off = 1; off < 16; off <<= 1)
                rs += __shfl_xor_sync(0xffffffffu, rs, off);
            lrow[ii] = lrow[ii] * corr + rs;
            mrow[ii] = mn;
            ULL c2 = pack2(corr, corr);
            fmul2(o2[ii][0], c2);
            fmul2(o2[ii][1], c2);
            *(float4*)&Ps[(ty * 4 + ii) * 64 + tx * 4] = make_float4(p0, p1, p2, p3);
        }
        __syncthreads();

        // O += P @ V
#pragma unroll 2
        for (int kk4 = 0; kk4 < 16; kk4++) {
            float4 pr[4];
            pr[0] = *(const float4*)&Ps[(ty * 4 + 0) * 64 + kk4 * 4];
            pr[1] = *(const float4*)&Ps[(ty * 4 + 1) * 64 + kk4 * 4];
            pr[2] = *(const float4*)&Ps[(ty * 4 + 2) * 64 + kk4 * 4];
            pr[3] = *(const float4*)&Ps[(ty * 4 + 3) * 64 + kk4 * 4];
#pragma unroll
            for (int u = 0; u < 4; u++) {
                ulonglong2 vv = *(const ulonglong2*)&Vs[(kk4 * 4 + u) * 64 + tx * 4];
#pragma unroll
                for (int ii = 0; ii < 4; ii++) {
                    float pe = ((const float*)&pr[ii])[u];
                    ULL ad = pack2(pe, pe);
                    ffma2(o2[ii][0], ad, vv.x);
                    ffma2(o2[ii][1], ad, vv.y);
                }
            }
        }
    }

    // epilogue: normalize and write to g_attn [B*S, HID], col = h*64 + d
    int row0 = qt * 64 + ty * 4;
#pragma unroll
    for (int ii = 0; ii < 4; ii++) {
        float rl = 1.0f / lrow[ii];
        float2 a = unpack2(o2[ii][0]);
        float2 c = unpack2(o2[ii][1]);
        float4 v = make_float4(a.x * rl, a.y * rl, c.x * rl, c.y * rl);
        long idx = ((long)(b * SEQ + row0 + ii) << 10) + h * HDIM + tx * 4;
        *(float4*)&g_attn[idx] = v;
    }
}

// ------------------------------- launch -------------------------------------
extern "C" void kernel_launch(void* const* d_in, const int* in_sizes, int n_in,
                              void* d_out, int out_size)
{
    const float* x     = (const float*)d_in[0];
    const float* W_qkv = (const float*)d_in[1];
    const float* b_qkv = (const float*)d_in[2];
    const float* W_out = (const float*)d_in[3];
    const float* b_out = (const float*)d_in[4];
    float* out = (float*)d_out;

    // 64 KB dynamic smem for the attention kernel (idempotent, capture-safe)
    cudaFuncSetAttribute(attn_kernel,
                         cudaFuncAttributeMaxDynamicSharedMemorySize, 65536);

    // 1) QKV projection + bias, scattered into [B,H,S,D] Q/K/V scratch
    sgemm_kernel<1><<<dim3(3 * HID / 128, MTOT / 128), 256>>>(
        x, W_qkv, b_qkv, nullptr, 3 * HID, HID);

    // 2) flash attention -> g_attn [B*S, HID]
    attn_kernel<<<dim3(SEQ / 64, HEADS, BATCH), 256, 65536>>>();

    // 3) output projection + bias
    sgemm_kernel<0><<<dim3(HID / 128, MTOT / 128), 256>>>(
        nullptr, W_out, b_out, out, HID, HID);
}

// round 16
// speedup vs baseline: 1.0005x; 1.0005x over previous
#include <cuda_runtime.h>

// ---------------------------------------------------------------------------
// MultiHeadAttention: x@W_qkv+b -> flash attention -> @W_out+b
// B=4, S=2048, HID=1024, H=16, D=64. All fp32.
// Uses sm_103a packed fp32 FMA (fma.rn.f32x2) for 2x fp32 throughput.
// ---------------------------------------------------------------------------

#define BATCH 4
#define SEQ   2048
#define HID   1024
#define HEADS 16
#define HDIM  64
#define MTOT  (BATCH * SEQ)   // 8192

typedef unsigned long long ULL;

// ------------------------- f32x2 helpers (sm_103a) -------------------------
__device__ __forceinline__ ULL pack2(float lo, float hi) {
    ULL r;
    asm("mov.b64 %0, {%1,%2};" : "=l"(r)
        : "r"(__float_as_uint(lo)), "r"(__float_as_uint(hi)));
    return r;
}
__device__ __forceinline__ float2 unpack2(ULL v) {
    unsigned int lo, hi;
    asm("mov.b64 {%0,%1}, %2;" : "=r"(lo), "=r"(hi) : "l"(v));
    return make_float2(__uint_as_float(lo), __uint_as_float(hi));
}
__device__ __forceinline__ void ffma2(ULL& d, ULL a, ULL b) {
    asm("fma.rn.f32x2 %0, %1, %2, %0;" : "+l"(d) : "l"(a), "l"(b));
}
__device__ __forceinline__ void fmul2(ULL& d, ULL a) {
    asm("mul.rn.f32x2 %0, %0, %1;" : "+l"(d) : "l"(a));
}

// ------------------------- scratch (device globals) ------------------------
__device__ __align__(128) float g_Q[BATCH * HEADS * SEQ * HDIM];
__device__ __align__(128) float g_K[BATCH * HEADS * SEQ * HDIM];
__device__ __align__(128) float g_V[BATCH * HEADS * SEQ * HDIM];
__device__ __align__(128) float g_attn[MTOT * HID];

// ------------------------- QKV scatter epilogue ----------------------------
__device__ __forceinline__ void store_qkv(int row, int n, float4 v) {
    // n in [0, 3072): chunk = n/1024 (0=Q,1=K,2=V), h = (n%1024)/64, d = n%64
    int chunk = n >> 10;
    int h = (n >> 6) & (HEADS - 1);
    int d = n & (HDIM - 1);
    int b = row >> 11;           // row / SEQ
    int s = row & (SEQ - 1);
    float* dst = (chunk == 0) ? g_Q : (chunk == 1) ? g_K : g_V;
    long idx = ((long)((b * HEADS + h) * SEQ + s) << 6) + d;
    *(float4*)&dst[idx] = v;
}

// ------------------------- SGEMM 128x128x16, 8x8/thread --------------------
// MODE 0: C[M,N] = A@B + bias  (A = g_attn when Ain==nullptr path? no: MODE)
// MODE 1: scatter into g_Q/g_K/g_V
template <int MODE>
__global__ __launch_bounds__(256, 2)
void sgemm_kernel(const float* __restrict__ Ain,
                  const float* __restrict__ Bmat,
                  const float* __restrict__ bias,
                  float* __restrict__ C,
                  int N, int K)
{
    __shared__ __align__(16) float As[16][128];  // k-major (transposed A tile)
    __shared__ __align__(16) float Bs[16][128];

    const float* A = (MODE == 0) ? (const float*)g_attn : Ain;

    int t  = threadIdx.x;
    int tx = t & 15;
    int ty = t >> 4;
    int m0 = blockIdx.y * 128;
    int n0 = blockIdx.x * 128;

    // global load assignments
    int ar = t >> 1;            // 0..127 (row within A tile)
    int ac = (t & 1) * 8;       // 0 or 8 (k offset)
    int br = t >> 4;            // 0..15 (k row of B tile)
    int bc = (t & 15) * 4;      // 0..60

    const float* Ap = A + (long)(m0 + ar) * K + ac;
    const float* Bp = Bmat + (long)br * N + n0 + bc;

    float4 ra0 = *(const float4*)(Ap);
    float4 ra1 = *(const float4*)(Ap + 4);
    float4 rb0 = *(const float4*)(Bp);
    float4 rb1 = *(const float4*)(Bp + 64);

    ULL acc[8][4];
#pragma unroll
    for (int i = 0; i < 8; i++)
#pragma unroll
        for (int j = 0; j < 4; j++) acc[i][j] = 0ULL;

    int nk = K >> 4;
    for (int kt = 0; kt < nk; kt++) {
        __syncthreads();
        // store staged tile (A transposed to k-major)
        As[ac + 0][ar] = ra0.x; As[ac + 1][ar] = ra0.y;
        As[ac + 2][ar] = ra0.z; As[ac + 3][ar] = ra0.w;
        As[ac + 4][ar] = ra1.x; As[ac + 5][ar] = ra1.y;
        As[ac + 6][ar] = ra1.z; As[ac + 7][ar] = ra1.w;
        *(float4*)&Bs[br][bc]      = rb0;
        *(float4*)&Bs[br][bc + 64] = rb1;
        __syncthreads();

        // prefetch next tile into registers (overlaps with compute)
        if (kt + 1 < nk) {
            const float* Ap2 = Ap + (kt + 1) * 16;
            const float* Bp2 = Bp + (long)(kt + 1) * 16 * N;
            ra0 = *(const float4*)(Ap2);
            ra1 = *(const float4*)(Ap2 + 4);
            rb0 = *(const float4*)(Bp2);
            rb1 = *(const float4*)(Bp2 + 64);
        }

#pragma unroll
        for (int k = 0; k < 16; k++) {
            float4 a0 = *(const float4*)&As[k][ty * 4];
            float4 a1 = *(const float4*)&As[k][64 + ty * 4];
            ulonglong2 b0 = *(const ulonglong2*)&Bs[k][tx * 4];
            ulonglong2 b1 = *(const ulonglong2*)&Bs[k][64 + tx * 4];
            ULL ad[8];
            ad[0] = pack2(a0.x, a0.x); ad[1] = pack2(a0.y, a0.y);
            ad[2] = pack2(a0.z, a0.z); ad[3] = pack2(a0.w, a0.w);
            ad[4] = pack2(a1.x, a1.x); ad[5] = pack2(a1.y, a1.y);
            ad[6] = pack2(a1.z, a1.z); ad[7] = pack2(a1.w, a1.w);
#pragma unroll
            for (int i = 0; i < 8; i++) {
                ffma2(acc[i][0], ad[i], b0.x);
                ffma2(acc[i][1], ad[i], b0.y);
                ffma2(acc[i][2], ad[i], b1.x);
                ffma2(acc[i][3], ad[i], b1.y);
            }
        }
    }

    // epilogue
    int c0 = n0 + tx * 4;
    int c1 = n0 + 64 + tx * 4;
    float4 bi0 = *(const float4*)&bias[c0];
    float4 bi1 = *(const float4*)&bias[c1];
#pragma unroll
    for (int i = 0; i < 8; i++) {
        int lr = (i < 4) ? (ty * 4 + i) : (64 + ty * 4 + i - 4);
        int gr = m0 + lr;
        float2 p0 = unpack2(acc[i][0]);
        float2 p1 = unpack2(acc[i][1]);
        float2 p2 = unpack2(acc[i][2]);
        float2 p3 = unpack2(acc[i][3]);
        float4 v0 = make_float4(p0.x + bi0.x, p0.y + bi0.y, p1.x + bi0.z, p1.y + bi0.w);
        float4 v1 = make_float4(p2.x + bi1.x, p2.y + bi1.y, p3.x + bi1.z, p3.y + bi1.w);
        if (MODE == 0) {
            *(float4*)&C[(long)gr * N + c0] = v0;
            *(float4*)&C[(long)gr * N + c1] = v1;
        } else {
            store_qkv(gr, c0, v0);
            store_qkv(gr, c1, v1);
        }
    }
}

// ------------------------- Flash attention (fp32) --------------------------
// One CTA per (b, h, 64-query tile). 256 threads = 16x16 logical grid.
// Smem: Qt(k-major) 16KB + Kt(k-major) 16KB + Vs 16KB + Ps 16KB = 64KB dynamic.
__global__ __launch_bounds__(256)
void attn_kernel()
{
    extern __shared__ __align__(16) float sm[];
    float* Qt = sm;            // [64 k][64 row]
    float* Kt = sm + 4096;     // [64 k][64 col]
    float* Vs = sm + 8192;     // [64 kv][64 d]
    float* Ps = sm + 12288;    // [64 row][64 kv]

    int t  = threadIdx.x;
    int tx = t & 15;
    int ty = t >> 4;
    int qt = blockIdx.x;
    int h  = blockIdx.y;
    int b  = blockIdx.z;

    long bh_base = (long)(b * HEADS + h) * SEQ * HDIM;
    const float* Qg = g_Q + bh_base + (long)qt * 64 * HDIM;
    const float* Kg = g_K + bh_base;
    const float* Vg = g_V + bh_base;

    int lr = t >> 2;            // 0..63
    int lc = (t & 3) * 16;      // 0,16,32,48

    // load Q tile transposed & pre-scaled by 1/sqrt(64)
#pragma unroll
    for (int q = 0; q < 4; q++) {
        int c = lc + q * 4;
        float4 v = *(const float4*)&Qg[lr * HDIM + c];
        Qt[(c + 0) * 64 + lr] = v.x * 0.125f;
        Qt[(c + 1) * 64 + lr] = v.y * 0.125f;
        Qt[(c + 2) * 64 + lr] = v.z * 0.125f;
        Qt[(c + 3) * 64 + lr] = v.w * 0.125f;
    }

    const float NEG_INF = __int_as_float(0xff800000);
    float mrow[4], lrow[4];
    ULL o2[4][2];
#pragma unroll
    for (int i = 0; i < 4; i++) {
        mrow[i] = NEG_INF; lrow[i] = 0.0f;
        o2[i][0] = 0ULL;   o2[i][1] = 0ULL;
    }

    for (int kt = 0; kt < SEQ / 64; kt++) {
        __syncthreads();   // previous PV done reading Vs/Ps (and Qt on iter 0)
        const float* Kgt = Kg + (long)kt * 64 * HDIM;
        const float* Vgt = Vg + (long)kt * 64 * HDIM;
#pragma unroll
        for (int q = 0; q < 4; q++) {
            int c = lc + q * 4;
            float4 kv = *(const float4*)&Kgt[lr * HDIM + c];
            Kt[(c + 0) * 64 + lr] = kv.x;
            Kt[(c + 1) * 64 + lr] = kv.y;
            Kt[(c + 2) * 64 + lr] = kv.z;
            Kt[(c + 3) * 64 + lr] = kv.w;
            *(float4*)&Vs[lr * 64 + c] = *(const float4*)&Vgt[lr * HDIM + c];
        }
        __syncthreads();

        // S = (Q*scale) @ K^T  -- 4x4 per thread, f32x2 packed
        ULL s2[4][2] = {{0ULL, 0ULL}, {0ULL, 0ULL}, {0ULL, 0ULL}, {0ULL, 0ULL}};
#pragma unroll 8
        for (int k = 0; k < 64; k++) {
            float4 a = *(const float4*)&Qt[k * 64 + ty * 4];
            ulonglong2 bv = *(const ulonglong2*)&Kt[k * 64 + tx * 4];
            ULL a0 = pack2(a.x, a.x), a1 = pack2(a.y, a.y);
            ULL a2 = pack2(a.z, a.z), a3 = pack2(a.w, a.w);
            ffma2(s2[0][0], a0, bv.x); ffma2(s2[0][1], a0, bv.y);
            ffma2(s2[1][0], a1, bv.x); ffma2(s2[1][1], a1, bv.y);
            ffma2(s2[2][0], a2, bv.x); ffma2(s2[2][1], a2, bv.y);
            ffma2(s2[3][0], a3, bv.x); ffma2(s2[3][1], a3, bv.y);
        }

        // online softmax (row stats replicated across the 16 tx lanes)
#pragma unroll
        for (int ii = 0; ii < 4; ii++) {
            float2 q0 = unpack2(s2[ii][0]);
            float2 q1 = unpack2(s2[ii][1]);
            float tmax = fmaxf(fmaxf(q0.x, q0.y), fmaxf(q1.x, q1.y));
#pragma unroll
            for (int off = 1; off < 16; off <<= 1)
                tmax = fmaxf(tmax, __shfl_xor_sync(0xffffffffu, tmax, off));
            float mn   = fmaxf(mrow[ii], tmax);
            float corr = __expf(mrow[ii] - mn);
            float p0 = __expf(q0.x - mn);
            float p1 = __expf(q0.y - mn);
            float p2 = __expf(q1.x - mn);
            float p3 = __expf(q1.y - mn);
            float rs = (p0 + p1) + (p2 + p3);
#pragma unroll
            for (int off = 1; off < 16; off <<= 1)
                rs += __shfl_xor_sync(0xffffffffu, rs, off);
            lrow[ii] = lrow[ii] * corr + rs;
            mrow[ii] = mn;
            ULL c2 = pack2(corr, corr);
            fmul2(o2[ii][0], c2);
            fmul2(o2[ii][1], c2);
            *(float4*)&Ps[(ty * 4 + ii) * 64 + tx * 4] = make_float4(p0, p1, p2, p3);
        }
        __syncthreads();

        // O += P @ V
#pragma unroll 2
        for (int kk4 = 0; kk4 < 16; kk4++) {
            float4 pr[4];
            pr[0] = *(const float4*)&Ps[(ty * 4 + 0) * 64 + kk4 * 4];
            pr[1] = *(const float4*)&Ps[(ty * 4 + 1) * 64 + kk4 * 4];
            pr[2] = *(const float4*)&Ps[(ty * 4 + 2) * 64 + kk4 * 4];
            pr[3] = *(const float4*)&Ps[(ty * 4 + 3) * 64 + kk4 * 4];
#pragma unroll
            for (int u = 0; u < 4; u++) {
                ulonglong2 vv = *(const ulonglong2*)&Vs[(kk4 * 4 + u) * 64 + tx * 4];
#pragma unroll
                for (int ii = 0; ii < 4; ii++) {
                    float pe = ((const float*)&pr[ii])[u];
                    ULL ad = pack2(pe, pe);
                    ffma2(o2[ii][0], ad, vv.x);
                    ffma2(o2[ii][1], ad, vv.y);
                }
            }
        }
    }

    // epilogue: normalize and write to g_attn [B*S, HID], col = h*64 + d
    int row0 = qt * 64 + ty * 4;
#pragma unroll
    for (int ii = 0; ii < 4; ii++) {
        float rl = 1.0f / lrow[ii];
        float2 a = unpack2(o2[ii][0]);
        float2 c = unpack2(o2[ii][1]);
        float4 v = make_float4(a.x * rl, a.y * rl, c.x * rl, c.y * rl);
        long idx = ((long)(b * SEQ + row0 + ii) << 10) + h * HDIM + tx * 4;
        *(float4*)&g_attn[idx] = v;
    }
}

// ------------------------------- launch -------------------------------------
extern "C" void kernel_launch(void* const* d_in, const int* in_sizes, int n_in,
                              void* d_out, int out_size)
{
    const float* x     = (const float*)d_in[0];
    const float* W_qkv = (const float*)d_in[1];
    const float* b_qkv = (const float*)d_in[2];
    const float* W_out = (const float*)d_in[3];
    const float* b_out = (const float*)d_in[4];
    float* out = (float*)d_out;

    // 64 KB dynamic smem for the attention kernel (idempotent, capture-safe)
    cudaFuncSetAttribute(attn_kernel,
                         cudaFuncAttributeMaxDynamicSharedMemorySize, 65536);

    // 1) QKV projection + bias, scattered into [B,H,S,D] Q/K/V scratch
    sgemm_kernel<1><<<dim3(3 * HID / 128, MTOT / 128), 256>>>(
        x, W_qkv, b_qkv, nullptr, 3 * HID, HID);

    // 2) flash attention -> g_attn [B*S, HID]
    attn_kernel<<<dim3(SEQ / 64, HEADS, BATCH), 256, 65536>>>();

    // 3) output projection + bias
    sgemm_kernel<0><<<dim3(HID / 128, MTOT / 128), 256>>>(
        nullptr, W_out, b_out, out, HID, HID);
}

// round 17
// speedup vs baseline: 1.0009x; 1.0004x over previous
#include <cuda_runtime.h>

// ---------------------------------------------------------------------------
// MultiHeadAttention: x@W_qkv+b -> flash attention -> @W_out+b
// B=4, S=2048, HID=1024, H=16, D=64. All fp32.
// Uses sm_103a packed fp32 FMA (fma.rn.f32x2) for 2x fp32 throughput.
// ---------------------------------------------------------------------------

#define BATCH 4
#define SEQ   2048
#define HID   1024
#define HEADS 16
#define HDIM  64
#define MTOT  (BATCH * SEQ)   // 8192

typedef unsigned long long ULL;

// ------------------------- f32x2 helpers (sm_103a) -------------------------
__device__ __forceinline__ ULL pack2(float lo, float hi) {
    ULL r;
    asm("mov.b64 %0, {%1,%2};" : "=l"(r)
        : "r"(__float_as_uint(lo)), "r"(__float_as_uint(hi)));
    return r;
}
__device__ __forceinline__ float2 unpack2(ULL v) {
    unsigned int lo, hi;
    asm("mov.b64 {%0,%1}, %2;" : "=r"(lo), "=r"(hi) : "l"(v));
    return make_float2(__uint_as_float(lo), __uint_as_float(hi));
}
__device__ __forceinline__ void ffma2(ULL& d, ULL a, ULL b) {
    asm("fma.rn.f32x2 %0, %1, %2, %0;" : "+l"(d) : "l"(a), "l"(b));
}
__device__ __forceinline__ void fmul2(ULL& d, ULL a) {
    asm("mul.rn.f32x2 %0, %0, %1;" : "+l"(d) : "l"(a));
}

// ------------------------- scratch (device globals) ------------------------
__device__ __align__(128) float g_Q[BATCH * HEADS * SEQ * HDIM];
__device__ __align__(128) float g_K[BATCH * HEADS * SEQ * HDIM];
__device__ __align__(128) float g_V[BATCH * HEADS * SEQ * HDIM];
__device__ __align__(128) float g_attn[MTOT * HID];

// ------------------------- QKV scatter epilogue ----------------------------
__device__ __forceinline__ void store_qkv(int row, int n, float4 v) {
    // n in [0, 3072): chunk = n/1024 (0=Q,1=K,2=V), h = (n%1024)/64, d = n%64
    int chunk = n >> 10;
    int h = (n >> 6) & (HEADS - 1);
    int d = n & (HDIM - 1);
    int b = row >> 11;           // row / SEQ
    int s = row & (SEQ - 1);
    float* dst = (chunk == 0) ? g_Q : (chunk == 1) ? g_K : g_V;
    long idx = ((long)((b * HEADS + h) * SEQ + s) << 6) + d;
    *(float4*)&dst[idx] = v;
}

// ------------------------- SGEMM 128x128x16, 8x8/thread --------------------
// MODE 0: C[M,N] = A@B + bias  (A = g_attn when Ain==nullptr path? no: MODE)
// MODE 1: scatter into g_Q/g_K/g_V
template <int MODE>
__global__ __launch_bounds__(256, 2)
void sgemm_kernel(const float* __restrict__ Ain,
                  const float* __restrict__ Bmat,
                  const float* __restrict__ bias,
                  float* __restrict__ C,
                  int N, int K)
{
    __shared__ __align__(16) float As[16][128];  // k-major (transposed A tile)
    __shared__ __align__(16) float Bs[16][128];

    const float* A = (MODE == 0) ? (const float*)g_attn : Ain;

    int t  = threadIdx.x;
    int tx = t & 15;
    int ty = t >> 4;
    int m0 = blockIdx.y * 128;
    int n0 = blockIdx.x * 128;

    // global load assignments
    int ar = t >> 1;            // 0..127 (row within A tile)
    int ac = (t & 1) * 8;       // 0 or 8 (k offset)
    int br = t >> 4;            // 0..15 (k row of B tile)
    int bc = (t & 15) * 4;      // 0..60

    const float* Ap = A + (long)(m0 + ar) * K + ac;
    const float* Bp = Bmat + (long)br * N + n0 + bc;

    float4 ra0 = *(const float4*)(Ap);
    float4 ra1 = *(const float4*)(Ap + 4);
    float4 rb0 = *(const float4*)(Bp);
    float4 rb1 = *(const float4*)(Bp + 64);

    ULL acc[8][4];
#pragma unroll
    for (int i = 0; i < 8; i++)
#pragma unroll
        for (int j = 0; j < 4; j++) acc[i][j] = 0ULL;

    int nk = K >> 4;
    for (int kt = 0; kt < nk; kt++) {
        __syncthreads();
        // store staged tile (A transposed to k-major)
        As[ac + 0][ar] = ra0.x; As[ac + 1][ar] = ra0.y;
        As[ac + 2][ar] = ra0.z; As[ac + 3][ar] = ra0.w;
        As[ac + 4][ar] = ra1.x; As[ac + 5][ar] = ra1.y;
        As[ac + 6][ar] = ra1.z; As[ac + 7][ar] = ra1.w;
        *(float4*)&Bs[br][bc]      = rb0;
        *(float4*)&Bs[br][bc + 64] = rb1;
        __syncthreads();

        // prefetch next tile into registers (overlaps with compute)
        if (kt + 1 < nk) {
            const float* Ap2 = Ap + (kt + 1) * 16;
            const float* Bp2 = Bp + (long)(kt + 1) * 16 * N;
            ra0 = *(const float4*)(Ap2);
            ra1 = *(const float4*)(Ap2 + 4);
            rb0 = *(const float4*)(Bp2);
            rb1 = *(const float4*)(Bp2 + 64);
        }

#pragma unroll
        for (int k = 0; k < 16; k++) {
            float4 a0 = *(const float4*)&As[k][ty * 4];
            float4 a1 = *(const float4*)&As[k][64 + ty * 4];
            ulonglong2 b0 = *(const ulonglong2*)&Bs[k][tx * 4];
            ulonglong2 b1 = *(const ulonglong2*)&Bs[k][64 + tx * 4];
            ULL ad[8];
            ad[0] = pack2(a0.x, a0.x); ad[1] = pack2(a0.y, a0.y);
            ad[2] = pack2(a0.z, a0.z); ad[3] = pack2(a0.w, a0.w);
            ad[4] = pack2(a1.x, a1.x); ad[5] = pack2(a1.y, a1.y);
            ad[6] = pack2(a1.z, a1.z); ad[7] = pack2(a1.w, a1.w);
#pragma unroll
            for (int i = 0; i < 8; i++) {
                ffma2(acc[i][0], ad[i], b0.x);
                ffma2(acc[i][1], ad[i], b0.y);
                ffma2(acc[i][2], ad[i], b1.x);
                ffma2(acc[i][3], ad[i], b1.y);
            }
        }
    }

    // epilogue
    int c0 = n0 + tx * 4;
    int c1 = n0 + 64 + tx * 4;
    float4 bi0 = *(const float4*)&bias[c0];
    float4 bi1 = *(const float4*)&bias[c1];
#pragma unroll
    for (int i = 0; i < 8; i++) {
        int lr = (i < 4) ? (ty * 4 + i) : (64 + ty * 4 + i - 4);
        int gr = m0 + lr;
        float2 p0 = unpack2(acc[i][0]);
        float2 p1 = unpack2(acc[i][1]);
        float2 p2 = unpack2(acc[i][2]);
        float2 p3 = unpack2(acc[i][3]);
        float4 v0 = make_float4(p0.x + bi0.x, p0.y + bi0.y, p1.x + bi0.z, p1.y + bi0.w);
        float4 v1 = make_float4(p2.x + bi1.x, p2.y + bi1.y, p3.x + bi1.z, p3.y + bi1.w);
        if (MODE == 0) {
            *(float4*)&C[(long)gr * N + c0] = v0;
            *(float4*)&C[(long)gr * N + c1] = v1;
        } else {
            store_qkv(gr, c0, v0);
            store_qkv(gr, c1, v1);
        }
    }
}

// ------------------------- Flash attention (fp32) --------------------------
// One CTA per (b, h, 64-query tile). 256 threads = 16x16 logical grid.
// Smem: Qt(k-major) 16KB + Kt(k-major) 16KB + Vs 16KB + Ps 16KB = 64KB dynamic.
__global__ __launch_bounds__(256)
void attn_kernel()
{
    extern __shared__ __align__(16) float sm[];
    float* Qt = sm;            // [64 k][64 row]
    float* Kt = sm + 4096;     // [64 k][64 col]
    float* Vs = sm + 8192;     // [64 kv][64 d]
    float* Ps = sm + 12288;    // [64 row][64 kv]

    int t  = threadIdx.x;
    int tx = t & 15;
    int ty = t >> 4;
    int qt = blockIdx.x;
    int h  = blockIdx.y;
    int b  = blockIdx.z;

    long bh_base = (long)(b * HEADS + h) * SEQ * HDIM;
    const float* Qg = g_Q + bh_base + (long)qt * 64 * HDIM;
    const float* Kg = g_K + bh_base;
    const float* Vg = g_V + bh_base;

    int lr = t >> 2;            // 0..63
    int lc = (t & 3) * 16;      // 0,16,32,48

    // load Q tile transposed & pre-scaled by 1/sqrt(64)
#pragma unroll
    for (int q = 0; q < 4; q++) {
        int c = lc + q * 4;
        float4 v = *(const float4*)&Qg[lr * HDIM + c];
        Qt[(c + 0) * 64 + lr] = v.x * 0.125f;
        Qt[(c + 1) * 64 + lr] = v.y * 0.125f;
        Qt[(c + 2) * 64 + lr] = v.z * 0.125f;
        Qt[(c + 3) * 64 + lr] = v.w * 0.125f;
    }

    const float NEG_INF = __int_as_float(0xff800000);
    float mrow[4], lrow[4];
    ULL o2[4][2];
#pragma unroll
    for (int i = 0; i < 4; i++) {
        mrow[i] = NEG_INF; lrow[i] = 0.0f;
        o2[i][0] = 0ULL;   o2[i][1] = 0ULL;
    }

    for (int kt = 0; kt < SEQ / 64; kt++) {
        __syncthreads();   // previous PV done reading Vs/Ps (and Qt on iter 0)
        const float* Kgt = Kg + (long)kt * 64 * HDIM;
        const float* Vgt = Vg + (long)kt * 64 * HDIM;
#pragma unroll
        for (int q = 0; q < 4; q++) {
            int c = lc + q * 4;
            float4 kv = *(const float4*)&Kgt[lr * HDIM + c];
            Kt[(c + 0) * 64 + lr] = kv.x;
            Kt[(c + 1) * 64 + lr] = kv.y;
            Kt[(c + 2) * 64 + lr] = kv.z;
            Kt[(c + 3) * 64 + lr] = kv.w;
            *(float4*)&Vs[lr * 64 + c] = *(const float4*)&Vgt[lr * HDIM + c];
        }
        __syncthreads();

        // S = (Q*scale) @ K^T  -- 4x4 per thread, f32x2 packed
        ULL s2[4][2] = {{0ULL, 0ULL}, {0ULL, 0ULL}, {0ULL, 0ULL}, {0ULL, 0ULL}};
#pragma unroll 8
        for (int k = 0; k < 64; k++) {
            float4 a = *(const float4*)&Qt[k * 64 + ty * 4];
            ulonglong2 bv = *(const ulonglong2*)&Kt[k * 64 + tx * 4];
            ULL a0 = pack2(a.x, a.x), a1 = pack2(a.y, a.y);
            ULL a2 = pack2(a.z, a.z), a3 = pack2(a.w, a.w);
            ffma2(s2[0][0], a0, bv.x); ffma2(s2[0][1], a0, bv.y);
            ffma2(s2[1][0], a1, bv.x); ffma2(s2[1][1], a1, bv.y);
            ffma2(s2[2][0], a2, bv.x); ffma2(s2[2][1], a2, bv.y);
            ffma2(s2[3][0], a3, bv.x); ffma2(s2[3][1], a3, bv.y);
        }

        // online softmax (row stats replicated across the 16 tx lanes)
#pragma unroll
        for (int ii = 0; ii < 4; ii++) {
            float2 q0 = unpack2(s2[ii][0]);
            float2 q1 = unpack2(s2[ii][1]);
            float tmax = fmaxf(fmaxf(q0.x, q0.y), fmaxf(q1.x, q1.y));
#pragma unroll
            for (int off = 1; off < 16; off <<= 1)
                tmax = fmaxf(tmax, __shfl_xor_sync(0xffffffffu, tmax, off));
            float mn   = fmaxf(mrow[ii], tmax);
            float corr = __expf(mrow[ii] - mn);
            float p0 = __expf(q0.x - mn);
            float p1 = __expf(q0.y - mn);
            float p2 = __expf(q1.x - mn);
            float p3 = __expf(q1.y - mn);
            float rs = (p0 + p1) + (p2 + p3);
#pragma unroll
            for (int off = 1; off < 16; off <<= 1)
                rs += __shfl_xor_sync(0xffffffffu, rs, off);
            lrow[ii] = lrow[ii] * corr + rs;
            mrow[ii] = mn;
            ULL c2 = pack2(corr, corr);
            fmul2(o2[ii][0], c2);
            fmul2(o2[ii][1], c2);
            *(float4*)&Ps[(ty * 4 + ii) * 64 + tx * 4] = make_float4(p0, p1, p2, p3);
        }
        __syncthreads();

        // O += P @ V
#pragma unroll 2
        for (int kk4 = 0; kk4 < 16; kk4++) {
            float4 pr[4];
            pr[0] = *(const float4*)&Ps[(ty * 4 + 0) * 64 + kk4 * 4];
            pr[1] = *(const float4*)&Ps[(ty * 4 + 1) * 64 + kk4 * 4];
            pr[2] = *(const float4*)&Ps[(ty * 4 + 2) * 64 + kk4 * 4];
            pr[3] = *(const float4*)&Ps[(ty * 4 + 3) * 64 + kk4 * 4];
#pragma unroll
            for (int u = 0; u < 4; u++) {
                ulonglong2 vv = *(const ulonglong2*)&Vs[(kk4 * 4 + u) * 64 + tx * 4];
#pragma unroll
                for (int ii = 0; ii < 4; ii++) {
                    float pe = ((const float*)&pr[ii])[u];
                    ULL ad = pack2(pe, pe);
                    ffma2(o2[ii][0], ad, vv.x);
                    ffma2(o2[ii][1], ad, vv.y);
                }
            }
        }
    }

    // epilogue: normalize and write to g_attn [B*S, HID], col = h*64 + d
    int row0 = qt * 64 + ty * 4;
#pragma unroll
    for (int ii = 0; ii < 4; ii++) {
        float rl = 1.0f / lrow[ii];
        float2 a = unpack2(o2[ii][0]);
        float2 c = unpack2(o2[ii][1]);
        float4 v = make_float4(a.x * rl, a.y * rl, c.x * rl, c.y * rl);
        long idx = ((long)(b * SEQ + row0 + ii) << 10) + h * HDIM + tx * 4;
        *(float4*)&g_attn[idx] = v;
    }
}

// ------------------------------- launch -------------------------------------
extern "C" void kernel_launch(void* const* d_in, const int* in_sizes, int n_in,
                              void* d_out, int out_size)
{
    const float* x     = (const float*)d_in[0];
    const float* W_qkv = (const float*)d_in[1];
    const float* b_qkv = (const float*)d_in[2];
    const float* W_out = (const float*)d_in[3];
    const float* b_out = (const float*)d_in[4];
    float* out = (float*)d_out;

    // 64 KB dynamic smem for the attention kernel (idempotent, capture-safe)
    cudaFuncSetAttribute(attn_kernel,
                         cudaFuncAttributeMaxDynamicSharedMemorySize, 65536);

    // 1) QKV projection + bias, scattered into [B,H,S,D] Q/K/V scratch
    sgemm_kernel<1><<<dim3(3 * HID / 128, MTOT / 128), 256>>>(
        x, W_qkv, b_qkv, nullptr, 3 * HID, HID);

    // 2) flash attention -> g_attn [B*S, HID]
    attn_kernel<<<dim3(SEQ / 64, HEADS, BATCH), 256, 65536>>>();

    // 3) output projection + bias
    sgemm_kernel<0><<<dim3(HID / 128, MTOT / 128), 256>>>(
        nullptr, W_out, b_out, out, HID, HID);
}